// round 1
// baseline (speedup 1.0000x reference)
#include <cuda_runtime.h>

// Problem constants (fixed by the reference)
#define G_   131072
#define NPG_ 38
#define NTOT (G_ * NPG_)        // 4,980,736 nodes
#define ETOT (10 * NTOT)        // 49,807,360 edges

// Scratch for per-node aggregate (init + atomics land here).
// ~19.9 MB static device array (allocation-free per harness rules).
__device__ float g_nodes[NTOT];

// ---------------------------------------------------------------------------
// Kernel 1: g_nodes = x * w_root + b_conv   (float4 vectorized)
// ---------------------------------------------------------------------------
__global__ void init_nodes_kernel(const float* __restrict__ x,
                                  const float* __restrict__ w_root,
                                  const float* __restrict__ b_conv) {
    int i = blockIdx.x * blockDim.x + threadIdx.x;   // over NTOT/4
    const float wr = __ldg(w_root);
    const float bc = __ldg(b_conv);
    float4 v = reinterpret_cast<const float4*>(x)[i];
    float4 o;
    o.x = fmaf(v.x, wr, bc);
    o.y = fmaf(v.y, wr, bc);
    o.z = fmaf(v.z, wr, bc);
    o.w = fmaf(v.w, wr, bc);
    reinterpret_cast<float4*>(g_nodes)[i] = o;
}

// ---------------------------------------------------------------------------
// Kernel 2: per-edge message + scatter-add
//   theta = edge_attr * w_edge + b_edge
//   g_nodes[dst] += x[src] * theta        (RED.ADD, no return value)
// 4 edges per thread; src/dst/attr read via 16B vector loads.
// ---------------------------------------------------------------------------
__global__ void edge_kernel(const int*   __restrict__ edge_index,
                            const float* __restrict__ edge_attr,
                            const float* __restrict__ x,
                            const float* __restrict__ w_edge,
                            const float* __restrict__ b_edge) {
    int i = blockIdx.x * blockDim.x + threadIdx.x;   // over ETOT/4
    const int4*   src4 = reinterpret_cast<const int4*>(edge_index);
    const int4*   dst4 = reinterpret_cast<const int4*>(edge_index + ETOT);
    const float4* ea4  = reinterpret_cast<const float4*>(edge_attr);

    int4   s = __ldg(&src4[i]);
    int4   d = __ldg(&dst4[i]);
    float4 a = __ldg(&ea4[i]);

    const float we = __ldg(w_edge);
    const float be = __ldg(b_edge);

    // gathers first (independent loads -> MLP), then the scatter-adds
    float x0 = __ldg(x + s.x);
    float x1 = __ldg(x + s.y);
    float x2 = __ldg(x + s.z);
    float x3 = __ldg(x + s.w);

    atomicAdd(g_nodes + d.x, x0 * fmaf(a.x, we, be));
    atomicAdd(g_nodes + d.y, x1 * fmaf(a.y, we, be));
    atomicAdd(g_nodes + d.z, x2 * fmaf(a.z, we, be));
    atomicAdd(g_nodes + d.w, x3 * fmaf(a.w, we, be));
}

// ---------------------------------------------------------------------------
// Kernel 3: per-graph head MLP 38 -> 4 -> 4 -> 12 + softmax
// 256 graphs per block, 1 thread per graph.
// Node features staged through shared (coalesced global read, pad 38->39
// to make the per-thread row reads bank-conflict-free).
// ---------------------------------------------------------------------------
#define GPB 256            // graphs per block
#define ROW 39             // padded row stride in shared

__global__ void head_kernel(const float* __restrict__ W1, const float* __restrict__ b1,
                            const float* __restrict__ W2, const float* __restrict__ b2,
                            const float* __restrict__ W3, const float* __restrict__ b3,
                            float* __restrict__ out) {
    __shared__ float sW1[NPG_ * 4];  // (38,4) row-major
    __shared__ float sb1[4];
    __shared__ float sW2[16];        // (4,4)
    __shared__ float sb2[4];
    __shared__ float sW3[48];        // (4,12)
    __shared__ float sb3[12];
    __shared__ float sn[GPB * ROW];

    const int t = threadIdx.x;

    if (t < NPG_ * 4) sW1[t] = W1[t];
    if (t < 4)        sb1[t] = b1[t];
    if (t < 16)       sW2[t] = W2[t];
    if (t >= 32 && t < 36) sb2[t - 32] = b2[t - 32];
    if (t >= 64 && t < 112) sW3[t - 64] = W3[t - 64];
    if (t >= 128 && t < 140) sb3[t - 128] = b3[t - 128];

    const long long g0 = (long long)blockIdx.x * GPB;
    const float* base = g_nodes + g0 * NPG_;

    // coalesced stage: GPB*38 contiguous floats -> padded shared rows
#pragma unroll 1
    for (int k = t; k < GPB * NPG_; k += blockDim.x) {
        int g = k / NPG_;
        int r = k - g * NPG_;
        sn[g * ROW + r] = base[k];
    }
    __syncthreads();

    const float* h0 = &sn[t * ROW];

    // layer 1: 38 -> 4
    float h1[4];
#pragma unroll
    for (int j = 0; j < 4; j++) h1[j] = sb1[j];
#pragma unroll
    for (int k = 0; k < NPG_; k++) {
        float v = h0[k];
#pragma unroll
        for (int j = 0; j < 4; j++) h1[j] = fmaf(v, sW1[k * 4 + j], h1[j]);
    }
#pragma unroll
    for (int j = 0; j < 4; j++) h1[j] = (h1[j] >= 0.0f) ? h1[j] : 0.01f * h1[j];

    // layer 2: 4 -> 4
    float h2[4];
#pragma unroll
    for (int j = 0; j < 4; j++) h2[j] = sb2[j];
#pragma unroll
    for (int k = 0; k < 4; k++) {
        float v = h1[k];
#pragma unroll
        for (int j = 0; j < 4; j++) h2[j] = fmaf(v, sW2[k * 4 + j], h2[j]);
    }
#pragma unroll
    for (int j = 0; j < 4; j++) h2[j] = (h2[j] >= 0.0f) ? h2[j] : 0.01f * h2[j];

    // layer 3: 4 -> 12 + leaky relu
    float h3[12];
#pragma unroll
    for (int j = 0; j < 12; j++) h3[j] = sb3[j];
#pragma unroll
    for (int k = 0; k < 4; k++) {
        float v = h2[k];
#pragma unroll
        for (int j = 0; j < 12; j++) h3[j] = fmaf(v, sW3[k * 12 + j], h3[j]);
    }
#pragma unroll
    for (int j = 0; j < 12; j++) h3[j] = (h3[j] >= 0.0f) ? h3[j] : 0.01f * h3[j];

    // softmax over 12 (stable)
    float m = h3[0];
#pragma unroll
    for (int j = 1; j < 12; j++) m = fmaxf(m, h3[j]);
    float ssum = 0.0f;
#pragma unroll
    for (int j = 0; j < 12; j++) {
        h3[j] = __expf(h3[j] - m);
        ssum += h3[j];
    }
    float inv = 1.0f / ssum;

    float* o = out + (g0 + t) * 12;
#pragma unroll
    for (int j = 0; j < 12; j++) o[j] = h3[j] * inv;
}

// ---------------------------------------------------------------------------
// Launch
// Inputs (metadata order): x, edge_index, edge_attr, w_edge, b_edge, w_root,
//                          b_conv, W1, b1, W2, b2, W3, b3
// ---------------------------------------------------------------------------
extern "C" void kernel_launch(void* const* d_in, const int* in_sizes, int n_in,
                              void* d_out, int out_size) {
    const float* x      = (const float*)d_in[0];
    const int*   ei     = (const int*)  d_in[1];
    const float* ea     = (const float*)d_in[2];
    const float* w_edge = (const float*)d_in[3];
    const float* b_edge = (const float*)d_in[4];
    const float* w_root = (const float*)d_in[5];
    const float* b_conv = (const float*)d_in[6];
    const float* W1     = (const float*)d_in[7];
    const float* b1     = (const float*)d_in[8];
    const float* W2     = (const float*)d_in[9];
    const float* b2     = (const float*)d_in[10];
    const float* W3     = (const float*)d_in[11];
    const float* b3     = (const float*)d_in[12];
    float* out = (float*)d_out;

    // 1) init node aggregate with root term:  NTOT/4 threads
    init_nodes_kernel<<<(NTOT / 4) / 256, 256>>>(x, w_root, b_conv);

    // 2) edge scatter: ETOT/4 threads
    edge_kernel<<<(ETOT / 4) / 256, 256>>>(ei, ea, x, w_edge, b_edge);

    // 3) head MLP + softmax: one thread per graph
    head_kernel<<<G_ / GPB, GPB>>>(W1, b1, W2, b2, W3, b3, out);
}